// round 16
// baseline (speedup 1.0000x reference)
#include <cuda_runtime.h>
#include <cstdint>

#define N_NODES 100000
#define E_EDGES 3200000
#define IN_DIM  256
#define OUT_DIM 64
#define LN_EPS  1e-5f
#define NEG_SLOPE 0.01f

// Scratch (no allocations allowed -> __device__ globals). 16B-aligned for v4 ops.
__device__ __align__(16) float g_deg[N_NODES];            // deg, then dinv after k_dinv
__device__ __align__(16) float g_hs [N_NODES * OUT_DIM];  // x@W (UNSCALED)
__device__ __align__(16) float g_acc[N_NODES * OUT_DIM];  // edge-message accumulator

// ---------------------------------------------------------------------------
// deg branch (forked stream): init -> deg scatter -> dinv
// ---------------------------------------------------------------------------
__global__ void k_init_deg() {
    int i = blockIdx.x * blockDim.x + threadIdx.x;
    if (i < N_NODES) g_deg[i] = 1.0f;                     // self-loop weight
}

__global__ void k_deg(const int* __restrict__ ei, const float* __restrict__ ew) {
    int e = blockIdx.x * blockDim.x + threadIdx.x;
    if (e < E_EDGES) atomicAdd(&g_deg[ei[E_EDGES + e]], ew[e]);
}

__global__ void k_dinv() {
    int i = blockIdx.x * blockDim.x + threadIdx.x;
    if (i < N_NODES) g_deg[i] = rsqrtf(g_deg[i]);         // in-place deg -> dinv
}

// ---------------------------------------------------------------------------
// GEMM (tf32 tensor cores, 3-term split) -> g_hs UNSCALED, g_acc = 0
// (No deg dependency -> runs concurrently with the deg branch.)
// ---------------------------------------------------------------------------
#define GEMM_ROWS 128
#define KC  128
#define SP  132          // padded smem stride -> frag bank = 4g+t (no conflict)
#define OSP 68

__device__ __forceinline__ uint32_t f2tf32(float f) {
    uint32_t r;
    asm("cvt.rna.tf32.f32 %0, %1;" : "=r"(r) : "f"(f));
    return r;
}

__device__ __forceinline__ void mma_tf32(float c[4], const uint32_t a[4],
                                         uint32_t b0, uint32_t b1) {
    asm volatile(
        "mma.sync.aligned.m16n8k8.row.col.f32.tf32.tf32.f32 "
        "{%0,%1,%2,%3}, {%4,%5,%6,%7}, {%8,%9}, {%0,%1,%2,%3};"
        : "+f"(c[0]), "+f"(c[1]), "+f"(c[2]), "+f"(c[3])
        : "r"(a[0]), "r"(a[1]), "r"(a[2]), "r"(a[3]), "r"(b0), "r"(b1));
}

__global__ void __launch_bounds__(256, 2) k_gemm(const float* __restrict__ x,
                                                 const float* __restrict__ W) {
    extern __shared__ float sm[];
    float* xs = sm;                       // [128][SP]
    float* wt = xs + GEMM_ROWS * SP;      // [64][SP]

    const int tid   = threadIdx.x;
    const int node0 = blockIdx.x * GEMM_ROWS;
    const int wid   = tid >> 5;
    const int lane  = tid & 31;
    const int g     = lane >> 2;
    const int t     = lane & 3;
    const int m0    = (wid & 3) * 16;
    const int nb    = (wid >> 2) * 64;

    float c[8][4];
    #pragma unroll
    for (int j = 0; j < 8; j++)
        #pragma unroll
        for (int q = 0; q < 4; q++) c[j][q] = 0.f;

    for (int ch = 0; ch < 2; ch++) {
        const int k0c = ch * KC;

        for (int i = 0; i < 8; i++) {
            int idx4 = tid + 256 * i;
            int n4   = idx4 & 15;
            int kk   = idx4 >> 4;
            float4 v = ((const float4*)W)[(size_t)(k0c + kk) * 16 + n4];
            wt[(n4 * 4 + 0) * SP + kk] = v.x;
            wt[(n4 * 4 + 1) * SP + kk] = v.y;
            wt[(n4 * 4 + 2) * SP + kk] = v.z;
            wt[(n4 * 4 + 3) * SP + kk] = v.w;
        }
        for (int i = 0; i < 16; i++) {
            int idx4 = tid + 256 * i;
            int k4   = idx4 & 31;
            int r    = idx4 >> 5;
            int gr   = node0 + r;
            float4 v = (gr < N_NODES)
                     ? ((const float4*)x)[(size_t)gr * 64 + (k0c >> 2) + k4]
                     : make_float4(0.f, 0.f, 0.f, 0.f);
            *(float4*)&xs[r * SP + k4 * 4] = v;
        }
        __syncthreads();

        #pragma unroll 4
        for (int ks = 0; ks < KC / 8; ks++) {
            const int k0 = ks * 8;
            float af[4];
            af[0] = wt[(m0 + g)     * SP + k0 + t];
            af[1] = wt[(m0 + g + 8) * SP + k0 + t];
            af[2] = wt[(m0 + g)     * SP + k0 + t + 4];
            af[3] = wt[(m0 + g + 8) * SP + k0 + t + 4];
            uint32_t ah[4], al[4];
            #pragma unroll
            for (int q = 0; q < 4; q++) {
                ah[q] = f2tf32(af[q]);
                al[q] = __float_as_uint(af[q] - __uint_as_float(ah[q]));
            }
            #pragma unroll
            for (int j = 0; j < 8; j++) {
                const int n0 = nb + j * 8;
                float b0f = xs[(n0 + g) * SP + k0 + t];
                float b1f = xs[(n0 + g) * SP + k0 + t + 4];
                uint32_t bh0 = f2tf32(b0f);
                uint32_t bh1 = f2tf32(b1f);
                uint32_t bl0 = __float_as_uint(b0f - __uint_as_float(bh0));
                uint32_t bl1 = __float_as_uint(b1f - __uint_as_float(bh1));
                mma_tf32(c[j], ah, bh0, bh1);
                mma_tf32(c[j], al, bh0, bh1);
                mma_tf32(c[j], ah, bl0, bl1);
            }
        }
        __syncthreads();
    }

    float* smo = sm;  // [128][OSP]
    #pragma unroll
    for (int j = 0; j < 8; j++) {
        const int nloc = nb + j * 8 + 2 * t;
        smo[(nloc)     * OSP + m0 + g]     = c[j][0];
        smo[(nloc + 1) * OSP + m0 + g]     = c[j][1];
        smo[(nloc)     * OSP + m0 + g + 8] = c[j][2];
        smo[(nloc + 1) * OSP + m0 + g + 8] = c[j][3];
    }
    __syncthreads();

    const float4 z4 = make_float4(0.f, 0.f, 0.f, 0.f);
    for (int i = 0; i < 8; i++) {
        int idx4 = tid + 256 * i;
        int r    = idx4 >> 4;
        int c4   = idx4 & 15;
        int gn   = node0 + r;
        if (gn < N_NODES) {
            float4 v = *(float4*)&smo[r * OSP + c4 * 4];
            ((float4*)g_hs)[(size_t)gn * 16 + c4]  = v;    // UNSCALED h
            ((float4*)g_acc)[(size_t)gn * 16 + c4] = z4;   // zero accumulator
        }
    }
}

// ---------------------------------------------------------------------------
// edge scatter (R4/R10 winner + dinv[src] folded into the edge weight):
// acc[dst] += (w * dinv[src]) * h[src]
// 16 threads/edge coalesced; 1 ld.v4 + 1 red.global.add.v4.f32 per lane.
// ---------------------------------------------------------------------------
__device__ __forceinline__ void red_v4(float* addr, float a, float b, float c, float d) {
    asm volatile("red.global.add.v4.f32 [%0], {%1, %2, %3, %4};"
                 :: "l"(addr), "f"(a), "f"(b), "f"(c), "f"(d) : "memory");
}

__global__ void __launch_bounds__(256) k_scatter(const int* __restrict__ ei,
                                                 const float* __restrict__ ew) {
    int t = blockIdx.x * blockDim.x + threadIdx.x;
    int e = t >> 4;
    if (e >= E_EDGES) return;
    int part = t & 15;

    const int   src = ei[e];
    const int   dst = ei[E_EDGES + e];
    const float w   = ew[e] * g_deg[src];     // g_deg holds dinv; broadcast load

    float4 m = *(const float4*)&g_hs[src * OUT_DIM + (part << 2)];
    red_v4(&g_acc[dst * OUT_DIM + (part << 2)], m.x * w, m.y * w, m.z * w, m.w * w);
}

// ---------------------------------------------------------------------------
// finalize: y = dinv*(acc + dinv*h) + b -> leaky_relu -> LayerNorm -> out
// one warp per node, 2 cols per lane
// ---------------------------------------------------------------------------
__global__ void k_finalize(const float* __restrict__ b, const float* __restrict__ gamma,
                           const float* __restrict__ beta, float* __restrict__ out) {
    int gw   = (blockIdx.x * blockDim.x + threadIdx.x) >> 5;
    int lane = threadIdx.x & 31;
    if (gw >= N_NODES) return;

    float dinv = g_deg[gw];                   // dinv (post k_dinv)
    int c0 = lane << 1;

    float2 a = *(const float2*)&g_acc[gw * OUT_DIM + c0];
    float2 h = *(const float2*)&g_hs [gw * OUT_DIM + c0];
    float y0 = dinv * (a.x + dinv * h.x) + b[c0];
    float y1 = dinv * (a.y + dinv * h.y) + b[c0 + 1];
    y0 = (y0 >= 0.f) ? y0 : NEG_SLOPE * y0;
    y1 = (y1 >= 0.f) ? y1 : NEG_SLOPE * y1;

    float s  = y0 + y1;
    float sq = y0 * y0 + y1 * y1;
    #pragma unroll
    for (int off = 16; off > 0; off >>= 1) {
        s  += __shfl_xor_sync(0xFFFFFFFFu, s,  off);
        sq += __shfl_xor_sync(0xFFFFFFFFu, sq, off);
    }
    float mu  = s * (1.f / 64.f);
    float var = sq * (1.f / 64.f) - mu * mu;
    float inv = rsqrtf(var + LN_EPS);

    float2 r;
    r.x = (y0 - mu) * inv * gamma[c0]     + beta[c0];
    r.y = (y1 - mu) * inv * gamma[c0 + 1] + beta[c0 + 1];
    *(float2*)&out[gw * OUT_DIM + c0] = r;
}

// ---------------------------------------------------------------------------
// Fork-join: {init_deg, deg, dinv} on a forked stream, concurrent with k_gemm.
// Event record/wait during capture become graph EDGES (no event nodes), so
// creating/destroying streams+events inside this call is capture-legal and
// allocation-free on the device.
// ---------------------------------------------------------------------------
extern "C" void kernel_launch(void* const* d_in, const int* in_sizes, int n_in,
                              void* d_out, int out_size) {
    const float* x     = (const float*)d_in[0];
    const int*   ei    = (const int*)  d_in[1];
    const float* ew    = (const float*)d_in[2];
    const float* W     = (const float*)d_in[3];
    const float* b     = (const float*)d_in[4];
    const float* gamma = (const float*)d_in[5];
    const float* beta  = (const float*)d_in[6];
    float* out = (float*)d_out;

    const int gemm_smem = (GEMM_ROWS * SP + OUT_DIM * SP) * (int)sizeof(float); // ~101KB
    cudaFuncSetAttribute(k_gemm, cudaFuncAttributeMaxDynamicSharedMemorySize, gemm_smem);

    cudaStream_t s1;
    cudaStreamCreateWithFlags(&s1, cudaStreamNonBlocking);
    cudaEvent_t evFork, evJoin;
    cudaEventCreateWithFlags(&evFork, cudaEventDisableTiming);
    cudaEventCreateWithFlags(&evJoin, cudaEventDisableTiming);

    // fork: deg branch on s1
    cudaEventRecord(evFork, 0);
    cudaStreamWaitEvent(s1, evFork, 0);
    k_init_deg<<<(N_NODES + 255) / 256, 256, 0, s1>>>();
    k_deg     <<<(E_EDGES + 255) / 256, 256, 0, s1>>>(ei, ew);
    k_dinv    <<<(N_NODES + 255) / 256, 256, 0, s1>>>();
    cudaEventRecord(evJoin, s1);

    // main stream: gemm runs concurrently with the deg branch
    k_gemm<<<(N_NODES + GEMM_ROWS - 1) / GEMM_ROWS, 256, gemm_smem>>>(x, W);

    // join, then the dependent tail
    cudaStreamWaitEvent(0, evJoin, 0);
    k_scatter <<<((long long)E_EDGES * 16 + 255) / 256, 256>>>(ei, ew);
    k_finalize<<<(N_NODES * 32 + 255) / 256, 256>>>(b, gamma, beta, out);

    cudaEventDestroy(evFork);
    cudaEventDestroy(evJoin);
    cudaStreamDestroy(s1);
}